// round 12
// baseline (speedup 1.0000x reference)
#include <cuda_runtime.h>
#include <cuda_bf16.h>
#include <math.h>

// ---------------------------------------------------------------------------
// NCA_3D  (B=8, C=16, S=64, HID=32, fp32)
// R12: smem-wavefront attack (L1 was 81% in R11):
//   - quad Sobel: 2h x 2w voxels x 4 channels / thread (96 LDS.64 vs 144)
//   - padded slab (h-stride 12, d-stride 72 floats): uniform 2-way LDS
//   - bit-mixed A-row permutation row' = [d1 h1 w0 h0 w2 w1 (w0^h0^d0)]:
//     STS 8-way -> 4-way, GEMM A loads stay conflict-free
//   smem 51.2KB (4 CTAs/SM either way; launch_bounds(128,4) -> 128 regs)
// ---------------------------------------------------------------------------

typedef unsigned int u32;

__device__ u32  g_w1t[32 * 64 / 2];    // bf16 [n=32][k=64], k = 4c+seg
__device__ u32  g_w2t[16 * 32 / 2];    // bf16 [n=16][k=32]
__device__ float g_alpha[8u << 18];

__device__ __forceinline__ u32 cvt_bf16x2(float hi, float lo) {
    u32 r; asm("cvt.rn.bf16x2.f32 %0, %1, %2;" : "=r"(r) : "f"(hi), "f"(lo)); return r;
}
__device__ __forceinline__ void mma16816(float* d, const u32* a, const u32* b) {
    asm("mma.sync.aligned.m16n8k16.row.col.f32.bf16.bf16.f32 "
        "{%0,%1,%2,%3}, {%4,%5,%6,%7}, {%8,%9}, {%0,%1,%2,%3};"
        : "+f"(d[0]), "+f"(d[1]), "+f"(d[2]), "+f"(d[3])
        : "r"(a[0]), "r"(a[1]), "r"(a[2]), "r"(a[3]), "r"(b[0]), "r"(b[1]));
}

// padded slab: w rows of 12 floats (10 used), 6 h-rows (stride 12), 6 d-planes (stride 72)
#define SLAB_CH   432         // floats per channel (6*72)
#define A_PITCH_U32 36        // 144 B row pitch
#define OFF_SLAB 0
#define OFF_A    27648        // 16*432*4
#define OFF_W1   46080        // + 128*144
#define OFF_W2   50176        // + 4096
#define SMEM_P1  51200        // + 1024

// ---------------------------------------------------------------------------
__global__ void nca_prep(const float* __restrict__ W1, const float* __restrict__ W2)
{
    int t = blockIdx.x * 256 + threadIdx.x;
    __nv_bfloat16* w1 = (__nv_bfloat16*)g_w1t;
    if (t < 32 * 64) {
        int n = t >> 6, k = t & 63;
        w1[t] = __float2bfloat16(W1[n * 64 + (k & 3) * 16 + (k >> 2)]);
    }
    __nv_bfloat16* w2 = (__nv_bfloat16*)g_w2t;
    if (t < 16 * 32)
        w2[t] = __float2bfloat16(W2[t]);
}

__global__ void nca_pad() {}

// ---------------------------------------------------------------------------
__global__ __launch_bounds__(128, 4)
void nca_pass1(const float* __restrict__ x, const float* __restrict__ rmask,
               const float* __restrict__ b1, float* __restrict__ out)
{
    extern __shared__ char smraw[];
    float* slab = (float*)(smraw + OFF_SLAB);
    u32*   Au   = (u32*)(smraw + OFF_A);
    u32*   w1u  = (u32*)(smraw + OFF_W1);
    u32*   w2u  = (u32*)(smraw + OFF_W2);

    int tid  = threadIdx.x;
    int warp = tid >> 5;
    int lane = tid & 31;
    int g = lane >> 2, c = lane & 3;

    int blk = blockIdx.x;
    int w0 = (blk & 7) << 3;
    int h0 = ((blk >> 3) & 15) << 2;
    int d0 = ((blk >> 7) & 15) << 2;
    int b  = blk >> 11;
    const size_t baseB = (size_t)b << 22;

    // ---- stage x slab into padded layout (wrap halo) ----
    for (int i = tid; i < 16 * 360; i += 128) {
        int ch = i / 360;
        int r = i - ch * 360;
        int sd = r / 60; r -= sd * 60;
        int sh = r / 10;
        int sw = r - sh * 10;
        int gd = (d0 + sd - 1) & 63;
        int gh = (h0 + sh - 1) & 63;
        int gw = (w0 + sw - 1) & 63;
        slab[ch * SLAB_CH + sd * 72 + sh * 12 + sw] =
            x[baseB + ((size_t)ch << 18) + ((size_t)gd << 12) + (gh << 6) + gw];
    }
    // ---- stage weights (uint4 copies of pre-converted images) ----
    {
        uint4* d1 = (uint4*)w1u; const uint4* s1 = (const uint4*)g_w1t;
        for (int i = tid; i < 256; i += 128) d1[i] = s1[i];
        uint4* d2 = (uint4*)w2u; const uint4* s2 = (const uint4*)g_w2t;
        if (tid < 64) d2[tid] = s2[tid];
    }
    __syncthreads();

    // ---- Sobel: quad (2h x 2w) x 4 channels per thread ----
    {
        int q = tid & 31;
        int chBase = (tid >> 5) << 2;                // warp -> channel group
        int vw0 = (q & 3) << 1;                      // 0,2,4,6
        int vh0 = ((q >> 2) & 1) << 1;               // 0,2
        int vd  = q >> 3;                            // 0..3
        int dlo = vd & 1, dhi = vd >> 1, hhi = vh0 >> 1;

        // 4 voxel row pointers (bit-mixed A layout), chBase*2 folded in
        u32* Rp[2][2];
#pragma unroll
        for (int hv = 0; hv < 2; hv++)
#pragma unroll
            for (int wv = 0; wv < 2; wv++) {
                int rowp = (dhi << 6) | (hhi << 5) | (wv << 4) | (hv << 3)
                         | ((vw0 >> 1) << 1) | (wv ^ hv ^ dlo);
                Rp[hv][wv] = Au + rowp * A_PITCH_U32 + chBase * 2;
            }

        const float2* s2b = (const float2*)(slab + chBase * SLAB_CH + vd * 72 + vh0 * 12 + vw0);

#pragma unroll 1
        for (int cc = 0; cc < 4; cc++) {
            const float2* p = s2b + cc * (SLAB_CH / 2);

            float a[16], m[16], xc[4];
            // plane 0
#pragma unroll
            for (int j = 0; j < 4; j++) {
                float2 q0 = p[j * 6], q1 = p[j * 6 + 1];
                a[j * 4 + 0] = q0.x; a[j * 4 + 1] = q0.y;
                a[j * 4 + 2] = q1.x; a[j * 4 + 3] = q1.y;
            }
#pragma unroll
            for (int k = 0; k < 16; k++) m[k] = a[k];
            // plane 1 (+ center saves)
#pragma unroll
            for (int j = 0; j < 4; j++) {
                float2 q0 = p[36 + j * 6], q1 = p[36 + j * 6 + 1];
                a[j * 4 + 0] = fmaf(2.f, q0.x, a[j * 4 + 0]);
                a[j * 4 + 1] = fmaf(2.f, q0.y, a[j * 4 + 1]);
                a[j * 4 + 2] = fmaf(2.f, q1.x, a[j * 4 + 2]);
                a[j * 4 + 3] = fmaf(2.f, q1.y, a[j * 4 + 3]);
                if (j == 1) { xc[0] = q0.y; xc[1] = q1.x; }
                if (j == 2) { xc[2] = q0.y; xc[3] = q1.x; }
            }
            // plane 2
#pragma unroll
            for (int j = 0; j < 4; j++) {
                float2 q0 = p[72 + j * 6], q1 = p[72 + j * 6 + 1];
                a[j * 4 + 0] += q0.x;  m[j * 4 + 0] = q0.x - m[j * 4 + 0];
                a[j * 4 + 1] += q0.y;  m[j * 4 + 1] = q0.y - m[j * 4 + 1];
                a[j * 4 + 2] += q1.x;  m[j * 4 + 2] = q1.x - m[j * 4 + 2];
                a[j * 4 + 3] += q1.y;  m[j * 4 + 3] = q1.y - m[j * 4 + 3];
            }

            float t0[4], t1[4], u0[4], u1[4], p0[4], p1[4];
#pragma unroll
            for (int k = 0; k < 4; k++) {
                t0[k] = fmaf(2.f, a[4 + k],  a[k]     + a[8 + k]);
                t1[k] = fmaf(2.f, a[8 + k],  a[4 + k] + a[12 + k]);
                u0[k] = a[8 + k]  - a[k];
                u1[k] = a[12 + k] - a[4 + k];
                p0[k] = fmaf(2.f, m[4 + k],  m[k]     + m[8 + k]);
                p1[k] = fmaf(2.f, m[8 + k],  m[4 + k] + m[12 + k]);
            }
            float gx00 = t0[2] - t0[0], gx01 = t0[3] - t0[1];
            float gx10 = t1[2] - t1[0], gx11 = t1[3] - t1[1];
            float gy00 = fmaf(2.f, u0[1], u0[0] + u0[2]);
            float gy01 = fmaf(2.f, u0[2], u0[1] + u0[3]);
            float gy10 = fmaf(2.f, u1[1], u1[0] + u1[2]);
            float gy11 = fmaf(2.f, u1[2], u1[1] + u1[3]);
            float gz00 = fmaf(2.f, p0[1], p0[0] + p0[2]);
            float gz01 = fmaf(2.f, p0[2], p0[1] + p0[3]);
            float gz10 = fmaf(2.f, p1[1], p1[0] + p1[2]);
            float gz11 = fmaf(2.f, p1[2], p1[1] + p1[3]);

            int ko = cc * 2;
            uint2 v00, v01, v10, v11;
            v00.x = cvt_bf16x2(gy00, gx00); v00.y = cvt_bf16x2(xc[0], gz00);
            v01.x = cvt_bf16x2(gy01, gx01); v01.y = cvt_bf16x2(xc[1], gz01);
            v10.x = cvt_bf16x2(gy10, gx10); v10.y = cvt_bf16x2(xc[2], gz10);
            v11.x = cvt_bf16x2(gy11, gx11); v11.y = cvt_bf16x2(xc[3], gz11);
            *(uint2*)(Rp[0][0] + ko) = v00;
            *(uint2*)(Rp[0][1] + ko) = v01;
            *(uint2*)(Rp[1][0] + ko) = v10;
            *(uint2*)(Rp[1][1] + ko) = v11;
        }
    }
    __syncthreads();

    // ---- GEMM1: M32 N32 K64 (bit-mixed A rows; conflict-free loads) ----
    // logical row r = warp*32 + mt*16 + g (h0=0) and r+8 (h0=1)
    int baseA0, baseB0, baseA1, baseB1;
    {
        int dhi = warp >> 1, dlo = warp & 1;
        int rA0 = (dhi << 6) | (0 << 5) | ((g & 1) << 4) | ((g >> 1) << 1) | ((g & 1) ^ dlo);
        int rB0 = rA0 ^ 8 ^ 1;
        int rA1 = rA0 | (1 << 5);
        int rB1 = rA1 ^ 8 ^ 1;
        baseA0 = rA0 * A_PITCH_U32 + c;  baseB0 = rB0 * A_PITCH_U32 + c;
        baseA1 = rA1 * A_PITCH_U32 + c;  baseB1 = rB1 * A_PITCH_U32 + c;
    }

    float C1[2][4][4];
#pragma unroll
    for (int mt = 0; mt < 2; mt++)
#pragma unroll
        for (int nt = 0; nt < 4; nt++)
#pragma unroll
            for (int qq = 0; qq < 4; qq++) C1[mt][nt][qq] = 0.f;

#pragma unroll
    for (int kt = 0; kt < 4; kt++) {
        u32 Bk[4][2];
#pragma unroll
        for (int nt = 0; nt < 4; nt++) {
            int idx = (g + 8 * nt) * 32 + 8 * kt + c;
            Bk[nt][0] = w1u[idx];
            Bk[nt][1] = w1u[idx + 4];
        }
#pragma unroll
        for (int mt = 0; mt < 2; mt++) {
            int bA = (mt ? baseA1 : baseA0) + 8 * kt;
            int bB = (mt ? baseB1 : baseB0) + 8 * kt;
            u32 a[4];
            a[0] = Au[bA];
            a[1] = Au[bB];
            a[2] = Au[bA + 4];
            a[3] = Au[bB + 4];
#pragma unroll
            for (int nt = 0; nt < 4; nt++)
                mma16816(C1[mt][nt], a, Bk[nt]);
        }
    }

    // ---- bias + relu ----
#pragma unroll
    for (int nt = 0; nt < 4; nt++) {
        float2 bp = *(const float2*)(b1 + 2 * c + 8 * nt);
#pragma unroll
        for (int mt = 0; mt < 2; mt++) {
            C1[mt][nt][0] = fmaxf(C1[mt][nt][0] + bp.x, 0.f);
            C1[mt][nt][1] = fmaxf(C1[mt][nt][1] + bp.y, 0.f);
            C1[mt][nt][2] = fmaxf(C1[mt][nt][2] + bp.x, 0.f);
            C1[mt][nt][3] = fmaxf(C1[mt][nt][3] + bp.y, 0.f);
        }
    }

    // ---- repack C1 -> A2 fragments ----
    u32 A2f[2][2][4];
#pragma unroll
    for (int mt = 0; mt < 2; mt++)
#pragma unroll
        for (int kt = 0; kt < 2; kt++) {
            A2f[mt][kt][0] = cvt_bf16x2(C1[mt][2 * kt][1],     C1[mt][2 * kt][0]);
            A2f[mt][kt][1] = cvt_bf16x2(C1[mt][2 * kt][3],     C1[mt][2 * kt][2]);
            A2f[mt][kt][2] = cvt_bf16x2(C1[mt][2 * kt + 1][1], C1[mt][2 * kt + 1][0]);
            A2f[mt][kt][3] = cvt_bf16x2(C1[mt][2 * kt + 1][3], C1[mt][2 * kt + 1][2]);
        }

    // ---- B2 fragments ----
    u32 B2f[2][2][2];
#pragma unroll
    for (int nt = 0; nt < 2; nt++)
#pragma unroll
        for (int kt = 0; kt < 2; kt++) {
            int idx = (g + 8 * nt) * 16 + 8 * kt + c;
            B2f[nt][kt][0] = w2u[idx];
            B2f[nt][kt][1] = w2u[idx + 4];
        }

    // ---- GEMM2: M32 N16 K32 ----
    float D2[2][2][4];
#pragma unroll
    for (int mt = 0; mt < 2; mt++)
#pragma unroll
        for (int nt = 0; nt < 2; nt++)
#pragma unroll
            for (int qq = 0; qq < 4; qq++) D2[mt][nt][qq] = 0.f;
#pragma unroll
    for (int kt = 0; kt < 2; kt++)
#pragma unroll
        for (int mt = 0; mt < 2; mt++)
#pragma unroll
            for (int nt = 0; nt < 2; nt++)
                mma16816(D2[mt][nt], A2f[mt][kt], B2f[nt][kt]);

    // ---- epilogue (logical voxel map unchanged; padded slab reads) ----
    {
        int vw = g, vd = warp;
        int d = d0 + vd, ww = w0 + vw;
#pragma unroll
        for (int mt = 0; mt < 2; mt++)
#pragma unroll
            for (int h2 = 0; h2 < 2; h2++) {
                int vh = mt * 2 + h2;
                int hh = h0 + vh;
                size_t sp = ((size_t)d << 12) + (hh << 6) + ww;
                int sctr = (vd + 1) * 72 + (vh + 1) * 12 + (vw + 1);
#pragma unroll
                for (int nt = 0; nt < 2; nt++)
#pragma unroll
                    for (int lh = 0; lh < 2; lh++) {
                        int ch = 2 * c + lh + 8 * nt;
                        float dy = D2[mt][nt][h2 * 2 + lh];
                        float xv = slab[ch * SLAB_CH + sctr];
                        size_t gi = baseB + ((size_t)ch << 18) + sp;
                        float u = floorf(rmask[gi] + 0.25f);
                        float y = fmaf(dy, u, xv);
                        out[gi] = y;
                        if (ch == 3) g_alpha[((size_t)b << 18) + sp] = y;
                    }
            }
    }
}

// ---------------------------------------------------------------------------
__global__ __launch_bounds__(256)
void nca_pass2(float* __restrict__ out)
{
    __shared__ float sa[600];

    int blk = blockIdx.x;
    int w0 = (blk & 7) << 3;
    int h0 = ((blk >> 3) & 7) << 3;
    int d0 = ((blk >> 6) & 15) << 2;
    int b  = blk >> 10;
    int tid = threadIdx.x;

    const float* ap = g_alpha + ((size_t)b << 18);
    for (int i = tid; i < 600; i += 256) {
        int dd = i / 100; int r = i - dd * 100;
        int hh = r / 10;  int ww = r - hh * 10;
        int gd = d0 + dd - 1, gh = h0 + hh - 1, gw = w0 + ww - 1;
        float val = -3.4e38f;
        if ((unsigned)gd < 64u && (unsigned)gh < 64u && (unsigned)gw < 64u)
            val = ap[((size_t)gd << 12) + (gh << 6) + gw];
        sa[i] = val;
    }
    __syncthreads();

    int wx = tid & 7, hy = (tid >> 3) & 7, dz = tid >> 6;
    const float* s = sa + dz * 100 + hy * 10 + wx;
    float m = -3.4e38f;
#pragma unroll
    for (int i = 0; i < 3; i++)
#pragma unroll
        for (int j = 0; j < 3; j++)
#pragma unroll
            for (int k = 0; k < 3; k++)
                m = fmaxf(m, s[i * 100 + j * 10 + k]);

    if (!(m > 0.1f)) {
        size_t sp = ((size_t)b << 22) + ((size_t)(d0 + dz) << 12) + ((h0 + hy) << 6) + (w0 + wx);
#pragma unroll
        for (int c = 0; c < 16; c++)
            out[sp + ((size_t)c << 18)] = 0.f;
    }
}

// ---------------------------------------------------------------------------
extern "C" void kernel_launch(void* const* d_in, const int* in_sizes, int n_in,
                              void* d_out, int out_size)
{
    const float* x   = (const float*)d_in[0];
    const float* rm  = (const float*)d_in[1];
    const float* W1  = (const float*)d_in[2];
    const float* b1  = (const float*)d_in[3];
    const float* W2  = (const float*)d_in[4];
    float* out = (float*)d_out;

    int B = in_sizes[0] >> 22;

    static int once = 0;
    if (!once) {
        cudaFuncSetAttribute(nca_pass1, cudaFuncAttributeMaxDynamicSharedMemorySize, SMEM_P1);
        once = 1;
    }

    // 5 launches/call; 4th overall = pass1 (ncu target slot)
    nca_prep<<<8, 256>>>(W1, W2);
    nca_pad<<<1, 32>>>();
    nca_pad<<<1, 32>>>();
    nca_pass1<<<B << 11, 128, SMEM_P1>>>(x, rm, b1, out);
    nca_pass2<<<B << 10, 256>>>(out);
}

// round 13
// speedup vs baseline: 1.2355x; 1.2355x over previous
#include <cuda_runtime.h>
#include <cuda_bf16.h>
#include <math.h>

// ---------------------------------------------------------------------------
// NCA_3D  (B=8, C=16, S=64, HID=32, fp32)
// R13: R11 (best, pass1=404us) + true 5 CTAs/SM:
//   - W2 smem stage dropped; B2f from global float2 AFTER GEMM1 (no R8 spills)
//   - smem 45568B (+1KB runtime reserve -> 46592/CTA, x5 = 232,960 <= 233,472)
//   - everything else identical to R11 (pair Sobel, per-kt B1 reload)
// ---------------------------------------------------------------------------

typedef unsigned int u32;

__device__ u32  g_w1t[32 * 64 / 2];    // bf16 [n=32][k=64], k = 4c+seg
__device__ float g_alpha[8u << 18];

__device__ __forceinline__ u32 cvt_bf16x2(float hi, float lo) {
    u32 r; asm("cvt.rn.bf16x2.f32 %0, %1, %2;" : "=r"(r) : "f"(hi), "f"(lo)); return r;
}
__device__ __forceinline__ void mma16816(float* d, const u32* a, const u32* b) {
    asm("mma.sync.aligned.m16n8k16.row.col.f32.bf16.bf16.f32 "
        "{%0,%1,%2,%3}, {%4,%5,%6,%7}, {%8,%9}, {%0,%1,%2,%3};"
        : "+f"(d[0]), "+f"(d[1]), "+f"(d[2]), "+f"(d[3])
        : "r"(a[0]), "r"(a[1]), "r"(a[2]), "r"(a[3]), "r"(b[0]), "r"(b[1]));
}

#define S_SLAB 360            // 6d x 6h x 10w per channel
#define A_PITCH_U32 36        // 144 B row pitch (conflict-free fragments)
#define OFF_SLAB 0
#define OFF_A    23040
#define OFF_W1   41472        // 4096 B
#define SMEM_P1  45568        // 5 CTAs/SM incl. 1KB runtime reserve

// ---------------------------------------------------------------------------
__global__ void nca_prep(const float* __restrict__ W1)
{
    int t = blockIdx.x * 256 + threadIdx.x;
    __nv_bfloat16* w1 = (__nv_bfloat16*)g_w1t;
    if (t < 32 * 64) {
        int n = t >> 6, k = t & 63;
        w1[t] = __float2bfloat16(W1[n * 64 + (k & 3) * 16 + (k >> 2)]);
    }
}

__global__ void nca_pad() {}

// ---------------------------------------------------------------------------
__global__ __launch_bounds__(128, 5)
void nca_pass1(const float* __restrict__ x, const float* __restrict__ rmask,
               const float* __restrict__ b1, const float* __restrict__ W2,
               float* __restrict__ out)
{
    extern __shared__ char smraw[];
    float* slab = (float*)(smraw + OFF_SLAB);
    u32*   Au   = (u32*)(smraw + OFF_A);
    u32*   w1u  = (u32*)(smraw + OFF_W1);

    int tid  = threadIdx.x;
    int warp = tid >> 5;
    int lane = tid & 31;
    int g = lane >> 2, c = lane & 3;

    int blk = blockIdx.x;
    int w0 = (blk & 7) << 3;
    int h0 = ((blk >> 3) & 15) << 2;
    int d0 = ((blk >> 7) & 15) << 2;
    int b  = blk >> 11;
    const size_t baseB = (size_t)b << 22;

    // ---- stage x slab (wrap halo) ----
    for (int i = tid; i < 16 * S_SLAB; i += 128) {
        int ch = i / S_SLAB;
        int r = i - ch * S_SLAB;
        int sd = r / 60; r -= sd * 60;
        int sh = r / 10;
        int sw = r - sh * 10;
        int gd = (d0 + sd - 1) & 63;
        int gh = (h0 + sh - 1) & 63;
        int gw = (w0 + sw - 1) & 63;
        slab[i] = x[baseB + ((size_t)ch << 18) + ((size_t)gd << 12) + (gh << 6) + gw];
    }
    // ---- stage W1 (uint4 copies of pre-converted image) ----
    {
        uint4* d1 = (uint4*)w1u; const uint4* s1 = (const uint4*)g_w1t;
        for (int i = tid; i < 256; i += 128) d1[i] = s1[i];
    }
    __syncthreads();

    // ---- Sobel: 2 voxels x 8 channels per thread, float2 shared taps ----
    {
        int pairIdx = tid & 63;
        int chBase  = (tid >> 6) << 3;
        int vd = pairIdx >> 4, vh = (pairIdx >> 2) & 3, vw0 = (pairIdx & 3) << 1;
        int r = vd * 32 + vh * 8 + vw0;
        u32* Arow0 = Au + r * A_PITCH_U32;
        u32* Arow1 = Arow0 + A_PITCH_U32;
        const float* sbase = slab + chBase * S_SLAB + vd * 60 + vh * 10 + vw0;

#pragma unroll 2
        for (int cc = 0; cc < 8; cc++) {
            const float2* s2 = (const float2*)(sbase + cc * S_SLAB);

            float v[36];
#pragma unroll
            for (int i = 0; i < 3; i++)
#pragma unroll
                for (int j = 0; j < 3; j++) {
                    int half = (i * 60 + j * 10) >> 1;
                    float2 p0 = s2[half];
                    float2 p1 = s2[half + 1];
                    int o4 = (i * 3 + j) * 4;
                    v[o4 + 0] = p0.x; v[o4 + 1] = p0.y;
                    v[o4 + 2] = p1.x; v[o4 + 3] = p1.y;
                }

            float a[12];
#pragma unroll
            for (int j = 0; j < 3; j++)
#pragma unroll
                for (int k = 0; k < 4; k++)
                    a[j * 4 + k] = fmaf(2.f, v[(3 + j) * 4 + k], v[j * 4 + k] + v[(6 + j) * 4 + k]);

            float gx0 = fmaf(2.f, a[4 + 2] - a[4 + 0], (a[2] - a[0]) + (a[8 + 2] - a[8 + 0]));
            float gx1 = fmaf(2.f, a[4 + 3] - a[4 + 1], (a[3] - a[1]) + (a[8 + 3] - a[8 + 1]));

            float e0 = a[8] - a[0], e1 = a[9] - a[1], e2 = a[10] - a[2], e3 = a[11] - a[3];
            float gy0 = fmaf(2.f, e1, e0 + e2);
            float gy1 = fmaf(2.f, e2, e1 + e3);

            float rr[4];
#pragma unroll
            for (int k = 0; k < 4; k++) {
                float q0 = v[24 + k] - v[k];
                float q1 = v[28 + k] - v[4 + k];
                float q2 = v[32 + k] - v[8 + k];
                rr[k] = fmaf(2.f, q1, q0 + q2);
            }
            float gz0 = fmaf(2.f, rr[1], rr[0] + rr[2]);
            float gz1 = fmaf(2.f, rr[2], rr[1] + rr[3]);

            float xc0 = v[16 + 1], xc1 = v[16 + 2];

            int ko = (chBase + cc) * 2;
            uint2 p0, p1;
            p0.x = cvt_bf16x2(gy0, gx0); p0.y = cvt_bf16x2(xc0, gz0);
            p1.x = cvt_bf16x2(gy1, gx1); p1.y = cvt_bf16x2(xc1, gz1);
            *(uint2*)(Arow0 + ko) = p0;
            *(uint2*)(Arow1 + ko) = p1;
        }
    }
    __syncthreads();

    // ---- GEMM1: M32 N32 K64 (B1 frags reloaded per kt: 8 live regs) ----
    float C1[2][4][4];
#pragma unroll
    for (int mt = 0; mt < 2; mt++)
#pragma unroll
        for (int nt = 0; nt < 4; nt++)
#pragma unroll
            for (int q = 0; q < 4; q++) C1[mt][nt][q] = 0.f;

#pragma unroll
    for (int kt = 0; kt < 4; kt++) {
        u32 Bk[4][2];
#pragma unroll
        for (int nt = 0; nt < 4; nt++) {
            int idx = (g + 8 * nt) * 32 + 8 * kt + c;
            Bk[nt][0] = w1u[idx];
            Bk[nt][1] = w1u[idx + 4];
        }
#pragma unroll
        for (int mt = 0; mt < 2; mt++) {
            int r = warp * 32 + mt * 16 + g;
            int base = r * A_PITCH_U32 + 8 * kt + c;
            u32 a[4];
            a[0] = Au[base];
            a[1] = Au[base + 8 * A_PITCH_U32];
            a[2] = Au[base + 4];
            a[3] = Au[base + 8 * A_PITCH_U32 + 4];
#pragma unroll
            for (int nt = 0; nt < 4; nt++)
                mma16816(C1[mt][nt], a, Bk[nt]);
        }
    }

    // ---- bias + relu (bias from global, L1-hit) ----
#pragma unroll
    for (int nt = 0; nt < 4; nt++) {
        float2 bp = *(const float2*)(b1 + 2 * c + 8 * nt);
#pragma unroll
        for (int mt = 0; mt < 2; mt++) {
            C1[mt][nt][0] = fmaxf(C1[mt][nt][0] + bp.x, 0.f);
            C1[mt][nt][1] = fmaxf(C1[mt][nt][1] + bp.y, 0.f);
            C1[mt][nt][2] = fmaxf(C1[mt][nt][2] + bp.x, 0.f);
            C1[mt][nt][3] = fmaxf(C1[mt][nt][3] + bp.y, 0.f);
        }
    }

    // ---- repack C1 -> A2 fragments (registers only) ----
    u32 A2f[2][2][4];
#pragma unroll
    for (int mt = 0; mt < 2; mt++)
#pragma unroll
        for (int kt = 0; kt < 2; kt++) {
            A2f[mt][kt][0] = cvt_bf16x2(C1[mt][2 * kt][1],     C1[mt][2 * kt][0]);
            A2f[mt][kt][1] = cvt_bf16x2(C1[mt][2 * kt][3],     C1[mt][2 * kt][2]);
            A2f[mt][kt][2] = cvt_bf16x2(C1[mt][2 * kt + 1][1], C1[mt][2 * kt + 1][0]);
            A2f[mt][kt][3] = cvt_bf16x2(C1[mt][2 * kt + 1][3], C1[mt][2 * kt + 1][2]);
        }

    // ---- B2 fragments from global (contiguous float2, L1-hit; built late) ----
    u32 B2f[2][2][2];
#pragma unroll
    for (int nt = 0; nt < 2; nt++)
#pragma unroll
        for (int kt = 0; kt < 2; kt++) {
            const float* W2r = W2 + (g + 8 * nt) * 32;
            float2 plo = *(const float2*)(W2r + 2 * (8 * kt + c));
            float2 phi = *(const float2*)(W2r + 2 * (8 * kt + c + 4));
            B2f[nt][kt][0] = cvt_bf16x2(plo.y, plo.x);
            B2f[nt][kt][1] = cvt_bf16x2(phi.y, phi.x);
        }

    // ---- GEMM2: M32 N16 K32 ----
    float D2[2][2][4];
#pragma unroll
    for (int mt = 0; mt < 2; mt++)
#pragma unroll
        for (int nt = 0; nt < 2; nt++)
#pragma unroll
            for (int q = 0; q < 4; q++) D2[mt][nt][q] = 0.f;
#pragma unroll
    for (int kt = 0; kt < 2; kt++)
#pragma unroll
        for (int mt = 0; mt < 2; mt++)
#pragma unroll
            for (int nt = 0; nt < 2; nt++)
                mma16816(D2[mt][nt], A2f[mt][kt], B2f[nt][kt]);

    // ---- epilogue ----
    {
        int vw = g, vd = warp;
        int d = d0 + vd, ww = w0 + vw;
#pragma unroll
        for (int mt = 0; mt < 2; mt++)
#pragma unroll
            for (int h2 = 0; h2 < 2; h2++) {
                int vh = mt * 2 + h2;
                int hh = h0 + vh;
                size_t sp = ((size_t)d << 12) + (hh << 6) + ww;
                int sctr = (vd + 1) * 60 + (vh + 1) * 10 + (vw + 1);
#pragma unroll
                for (int nt = 0; nt < 2; nt++)
#pragma unroll
                    for (int lh = 0; lh < 2; lh++) {
                        int ch = 2 * c + lh + 8 * nt;
                        float dy = D2[mt][nt][h2 * 2 + lh];
                        float xv = slab[ch * S_SLAB + sctr];
                        size_t gi = baseB + ((size_t)ch << 18) + sp;
                        float u = floorf(rmask[gi] + 0.25f);
                        float y = fmaf(dy, u, xv);
                        out[gi] = y;
                        if (ch == 3) g_alpha[((size_t)b << 18) + sp] = y;
                    }
            }
    }
}

// ---------------------------------------------------------------------------
__global__ __launch_bounds__(256)
void nca_pass2(float* __restrict__ out)
{
    __shared__ float sa[600];

    int blk = blockIdx.x;
    int w0 = (blk & 7) << 3;
    int h0 = ((blk >> 3) & 7) << 3;
    int d0 = ((blk >> 6) & 15) << 2;
    int b  = blk >> 10;
    int tid = threadIdx.x;

    const float* ap = g_alpha + ((size_t)b << 18);
    for (int i = tid; i < 600; i += 256) {
        int dd = i / 100; int r = i - dd * 100;
        int hh = r / 10;  int ww = r - hh * 10;
        int gd = d0 + dd - 1, gh = h0 + hh - 1, gw = w0 + ww - 1;
        float val = -3.4e38f;
        if ((unsigned)gd < 64u && (unsigned)gh < 64u && (unsigned)gw < 64u)
            val = ap[((size_t)gd << 12) + (gh << 6) + gw];
        sa[i] = val;
    }
    __syncthreads();

    int wx = tid & 7, hy = (tid >> 3) & 7, dz = tid >> 6;
    const float* s = sa + dz * 100 + hy * 10 + wx;
    float m = -3.4e38f;
#pragma unroll
    for (int i = 0; i < 3; i++)
#pragma unroll
        for (int j = 0; j < 3; j++)
#pragma unroll
            for (int k = 0; k < 3; k++)
                m = fmaxf(m, s[i * 100 + j * 10 + k]);

    if (!(m > 0.1f)) {
        size_t sp = ((size_t)b << 22) + ((size_t)(d0 + dz) << 12) + ((h0 + hy) << 6) + (w0 + wx);
#pragma unroll
        for (int c = 0; c < 16; c++)
            out[sp + ((size_t)c << 18)] = 0.f;
    }
}

// ---------------------------------------------------------------------------
extern "C" void kernel_launch(void* const* d_in, const int* in_sizes, int n_in,
                              void* d_out, int out_size)
{
    const float* x   = (const float*)d_in[0];
    const float* rm  = (const float*)d_in[1];
    const float* W1  = (const float*)d_in[2];
    const float* b1  = (const float*)d_in[3];
    const float* W2  = (const float*)d_in[4];
    float* out = (float*)d_out;

    int B = in_sizes[0] >> 22;

    static int once = 0;
    if (!once) {
        cudaFuncSetAttribute(nca_pass1, cudaFuncAttributeMaxDynamicSharedMemorySize, SMEM_P1);
        once = 1;
    }

    // 5 launches/call; 4th overall = pass1 (ncu target slot)
    nca_prep<<<8, 256>>>(W1);
    nca_pad<<<1, 32>>>();
    nca_pad<<<1, 32>>>();
    nca_pass1<<<B << 11, 128, SMEM_P1>>>(x, rm, b1, W2, out);
    nca_pass2<<<B << 10, 256>>>(out);
}

// round 14
// speedup vs baseline: 1.3217x; 1.0698x over previous
#include <cuda_runtime.h>
#include <cuda_bf16.h>
#include <math.h>

// ---------------------------------------------------------------------------
// NCA_3D  (B=8, C=16, S=64, HID=32, fp32)
// R14: R13 + XOR-swizzled W1 smem image.
//   R13's Bk loads were 8-WAY BANK CONFLICTED (idx mod 32 = 8kt+c for all g).
//   Store word at n*32 + (k2 ^ ((n&7)<<2)) -> load bank (8kt+c)^4g: all 32
//   lanes distinct -> conflict-free. ~1024 wavefronts/CTA removed.
// ---------------------------------------------------------------------------

typedef unsigned int u32;

__device__ u32  g_w1t[32 * 32];        // u32 pairs, [n][k2 ^ ((n&7)<<2)]
__device__ float g_alpha[8u << 18];

__device__ __forceinline__ u32 cvt_bf16x2(float hi, float lo) {
    u32 r; asm("cvt.rn.bf16x2.f32 %0, %1, %2;" : "=r"(r) : "f"(hi), "f"(lo)); return r;
}
__device__ __forceinline__ void mma16816(float* d, const u32* a, const u32* b) {
    asm("mma.sync.aligned.m16n8k16.row.col.f32.bf16.bf16.f32 "
        "{%0,%1,%2,%3}, {%4,%5,%6,%7}, {%8,%9}, {%0,%1,%2,%3};"
        : "+f"(d[0]), "+f"(d[1]), "+f"(d[2]), "+f"(d[3])
        : "r"(a[0]), "r"(a[1]), "r"(a[2]), "r"(a[3]), "r"(b[0]), "r"(b[1]));
}

#define S_SLAB 360            // 6d x 6h x 10w per channel
#define A_PITCH_U32 36        // 144 B row pitch (conflict-free fragments)
#define OFF_SLAB 0
#define OFF_A    23040
#define OFF_W1   41472        // 4096 B
#define SMEM_P1  45568        // 5 CTAs/SM incl. runtime reserve

// ---------------------------------------------------------------------------
__global__ void nca_prep(const float* __restrict__ W1)
{
    int t = blockIdx.x * 256 + threadIdx.x;
    __nv_bfloat16* w1 = (__nv_bfloat16*)g_w1t;
    if (t < 32 * 64) {
        int n = t >> 6, k = t & 63;
        // logical k = 4c'+seg  ->  W1[n*64 + seg*16 + c']
        float w = W1[n * 64 + (k & 3) * 16 + (k >> 2)];
        int k2 = k >> 1;
        int sw = k2 ^ ((n & 7) << 2);            // XOR swizzle
        w1[(n * 32 + sw) * 2 + (k & 1)] = __float2bfloat16(w);
    }
}

__global__ void nca_pad() {}

// ---------------------------------------------------------------------------
__global__ __launch_bounds__(128, 5)
void nca_pass1(const float* __restrict__ x, const float* __restrict__ rmask,
               const float* __restrict__ b1, const float* __restrict__ W2,
               float* __restrict__ out)
{
    extern __shared__ char smraw[];
    float* slab = (float*)(smraw + OFF_SLAB);
    u32*   Au   = (u32*)(smraw + OFF_A);
    u32*   w1u  = (u32*)(smraw + OFF_W1);

    int tid  = threadIdx.x;
    int warp = tid >> 5;
    int lane = tid & 31;
    int g = lane >> 2, c = lane & 3;

    int blk = blockIdx.x;
    int w0 = (blk & 7) << 3;
    int h0 = ((blk >> 3) & 15) << 2;
    int d0 = ((blk >> 7) & 15) << 2;
    int b  = blk >> 11;
    const size_t baseB = (size_t)b << 22;

    // ---- stage x slab (wrap halo) ----
    for (int i = tid; i < 16 * S_SLAB; i += 128) {
        int ch = i / S_SLAB;
        int r = i - ch * S_SLAB;
        int sd = r / 60; r -= sd * 60;
        int sh = r / 10;
        int sw = r - sh * 10;
        int gd = (d0 + sd - 1) & 63;
        int gh = (h0 + sh - 1) & 63;
        int gw = (w0 + sw - 1) & 63;
        slab[i] = x[baseB + ((size_t)ch << 18) + ((size_t)gd << 12) + (gh << 6) + gw];
    }
    // ---- stage W1 (uint4 copies of pre-swizzled image) ----
    {
        uint4* d1 = (uint4*)w1u; const uint4* s1 = (const uint4*)g_w1t;
        for (int i = tid; i < 256; i += 128) d1[i] = s1[i];
    }
    __syncthreads();

    // ---- Sobel: 2 voxels x 8 channels per thread, float2 shared taps ----
    {
        int pairIdx = tid & 63;
        int chBase  = (tid >> 6) << 3;
        int vd = pairIdx >> 4, vh = (pairIdx >> 2) & 3, vw0 = (pairIdx & 3) << 1;
        int r = vd * 32 + vh * 8 + vw0;
        u32* Arow0 = Au + r * A_PITCH_U32;
        u32* Arow1 = Arow0 + A_PITCH_U32;
        const float* sbase = slab + chBase * S_SLAB + vd * 60 + vh * 10 + vw0;

#pragma unroll 2
        for (int cc = 0; cc < 8; cc++) {
            const float2* s2 = (const float2*)(sbase + cc * S_SLAB);

            float v[36];
#pragma unroll
            for (int i = 0; i < 3; i++)
#pragma unroll
                for (int j = 0; j < 3; j++) {
                    int half = (i * 60 + j * 10) >> 1;
                    float2 p0 = s2[half];
                    float2 p1 = s2[half + 1];
                    int o4 = (i * 3 + j) * 4;
                    v[o4 + 0] = p0.x; v[o4 + 1] = p0.y;
                    v[o4 + 2] = p1.x; v[o4 + 3] = p1.y;
                }

            float a[12];
#pragma unroll
            for (int j = 0; j < 3; j++)
#pragma unroll
                for (int k = 0; k < 4; k++)
                    a[j * 4 + k] = fmaf(2.f, v[(3 + j) * 4 + k], v[j * 4 + k] + v[(6 + j) * 4 + k]);

            float gx0 = fmaf(2.f, a[4 + 2] - a[4 + 0], (a[2] - a[0]) + (a[8 + 2] - a[8 + 0]));
            float gx1 = fmaf(2.f, a[4 + 3] - a[4 + 1], (a[3] - a[1]) + (a[8 + 3] - a[8 + 1]));

            float e0 = a[8] - a[0], e1 = a[9] - a[1], e2 = a[10] - a[2], e3 = a[11] - a[3];
            float gy0 = fmaf(2.f, e1, e0 + e2);
            float gy1 = fmaf(2.f, e2, e1 + e3);

            float rr[4];
#pragma unroll
            for (int k = 0; k < 4; k++) {
                float q0 = v[24 + k] - v[k];
                float q1 = v[28 + k] - v[4 + k];
                float q2 = v[32 + k] - v[8 + k];
                rr[k] = fmaf(2.f, q1, q0 + q2);
            }
            float gz0 = fmaf(2.f, rr[1], rr[0] + rr[2]);
            float gz1 = fmaf(2.f, rr[2], rr[1] + rr[3]);

            float xc0 = v[16 + 1], xc1 = v[16 + 2];

            int ko = (chBase + cc) * 2;
            uint2 p0, p1;
            p0.x = cvt_bf16x2(gy0, gx0); p0.y = cvt_bf16x2(xc0, gz0);
            p1.x = cvt_bf16x2(gy1, gx1); p1.y = cvt_bf16x2(xc1, gz1);
            *(uint2*)(Arow0 + ko) = p0;
            *(uint2*)(Arow1 + ko) = p1;
        }
    }
    __syncthreads();

    // ---- GEMM1: M32 N32 K64 (swizzled, conflict-free Bk loads) ----
    float C1[2][4][4];
#pragma unroll
    for (int mt = 0; mt < 2; mt++)
#pragma unroll
        for (int nt = 0; nt < 4; nt++)
#pragma unroll
            for (int q = 0; q < 4; q++) C1[mt][nt][q] = 0.f;

    const int sw4g = g << 2;     // XOR term: (n&7)<<2 with n = g+8nt
#pragma unroll
    for (int kt = 0; kt < 4; kt++) {
        u32 Bk[4][2];
#pragma unroll
        for (int nt = 0; nt < 4; nt++) {
            int rowb = (g + 8 * nt) * 32;
            Bk[nt][0] = w1u[rowb + ((8 * kt + c) ^ sw4g)];
            Bk[nt][1] = w1u[rowb + ((8 * kt + c + 4) ^ sw4g)];
        }
#pragma unroll
        for (int mt = 0; mt < 2; mt++) {
            int r = warp * 32 + mt * 16 + g;
            int base = r * A_PITCH_U32 + 8 * kt + c;
            u32 a[4];
            a[0] = Au[base];
            a[1] = Au[base + 8 * A_PITCH_U32];
            a[2] = Au[base + 4];
            a[3] = Au[base + 8 * A_PITCH_U32 + 4];
#pragma unroll
            for (int nt = 0; nt < 4; nt++)
                mma16816(C1[mt][nt], a, Bk[nt]);
        }
    }

    // ---- bias + relu (bias from global, L1-hit) ----
#pragma unroll
    for (int nt = 0; nt < 4; nt++) {
        float2 bp = *(const float2*)(b1 + 2 * c + 8 * nt);
#pragma unroll
        for (int mt = 0; mt < 2; mt++) {
            C1[mt][nt][0] = fmaxf(C1[mt][nt][0] + bp.x, 0.f);
            C1[mt][nt][1] = fmaxf(C1[mt][nt][1] + bp.y, 0.f);
            C1[mt][nt][2] = fmaxf(C1[mt][nt][2] + bp.x, 0.f);
            C1[mt][nt][3] = fmaxf(C1[mt][nt][3] + bp.y, 0.f);
        }
    }

    // ---- repack C1 -> A2 fragments (registers only) ----
    u32 A2f[2][2][4];
#pragma unroll
    for (int mt = 0; mt < 2; mt++)
#pragma unroll
        for (int kt = 0; kt < 2; kt++) {
            A2f[mt][kt][0] = cvt_bf16x2(C1[mt][2 * kt][1],     C1[mt][2 * kt][0]);
            A2f[mt][kt][1] = cvt_bf16x2(C1[mt][2 * kt][3],     C1[mt][2 * kt][2]);
            A2f[mt][kt][2] = cvt_bf16x2(C1[mt][2 * kt + 1][1], C1[mt][2 * kt + 1][0]);
            A2f[mt][kt][3] = cvt_bf16x2(C1[mt][2 * kt + 1][3], C1[mt][2 * kt + 1][2]);
        }

    // ---- B2 fragments from global (contiguous float2, L1-hit; built late) ----
    u32 B2f[2][2][2];
#pragma unroll
    for (int nt = 0; nt < 2; nt++)
#pragma unroll
        for (int kt = 0; kt < 2; kt++) {
            const float* W2r = W2 + (g + 8 * nt) * 32;
            float2 plo = *(const float2*)(W2r + 2 * (8 * kt + c));
            float2 phi = *(const float2*)(W2r + 2 * (8 * kt + c + 4));
            B2f[nt][kt][0] = cvt_bf16x2(plo.y, plo.x);
            B2f[nt][kt][1] = cvt_bf16x2(phi.y, phi.x);
        }

    // ---- GEMM2: M32 N16 K32 ----
    float D2[2][2][4];
#pragma unroll
    for (int mt = 0; mt < 2; mt++)
#pragma unroll
        for (int nt = 0; nt < 2; nt++)
#pragma unroll
            for (int q = 0; q < 4; q++) D2[mt][nt][q] = 0.f;
#pragma unroll
    for (int kt = 0; kt < 2; kt++)
#pragma unroll
        for (int mt = 0; mt < 2; mt++)
#pragma unroll
            for (int nt = 0; nt < 2; nt++)
                mma16816(D2[mt][nt], A2f[mt][kt], B2f[nt][kt]);

    // ---- epilogue ----
    {
        int vw = g, vd = warp;
        int d = d0 + vd, ww = w0 + vw;
#pragma unroll
        for (int mt = 0; mt < 2; mt++)
#pragma unroll
            for (int h2 = 0; h2 < 2; h2++) {
                int vh = mt * 2 + h2;
                int hh = h0 + vh;
                size_t sp = ((size_t)d << 12) + (hh << 6) + ww;
                int sctr = (vd + 1) * 60 + (vh + 1) * 10 + (vw + 1);
#pragma unroll
                for (int nt = 0; nt < 2; nt++)
#pragma unroll
                    for (int lh = 0; lh < 2; lh++) {
                        int ch = 2 * c + lh + 8 * nt;
                        float dy = D2[mt][nt][h2 * 2 + lh];
                        float xv = slab[ch * S_SLAB + sctr];
                        size_t gi = baseB + ((size_t)ch << 18) + sp;
                        float u = floorf(rmask[gi] + 0.25f);
                        float y = fmaf(dy, u, xv);
                        out[gi] = y;
                        if (ch == 3) g_alpha[((size_t)b << 18) + sp] = y;
                    }
            }
    }
}

// ---------------------------------------------------------------------------
__global__ __launch_bounds__(256)
void nca_pass2(float* __restrict__ out)
{
    __shared__ float sa[600];

    int blk = blockIdx.x;
    int w0 = (blk & 7) << 3;
    int h0 = ((blk >> 3) & 7) << 3;
    int d0 = ((blk >> 6) & 15) << 2;
    int b  = blk >> 10;
    int tid = threadIdx.x;

    const float* ap = g_alpha + ((size_t)b << 18);
    for (int i = tid; i < 600; i += 256) {
        int dd = i / 100; int r = i - dd * 100;
        int hh = r / 10;  int ww = r - hh * 10;
        int gd = d0 + dd - 1, gh = h0 + hh - 1, gw = w0 + ww - 1;
        float val = -3.4e38f;
        if ((unsigned)gd < 64u && (unsigned)gh < 64u && (unsigned)gw < 64u)
            val = ap[((size_t)gd << 12) + (gh << 6) + gw];
        sa[i] = val;
    }
    __syncthreads();

    int wx = tid & 7, hy = (tid >> 3) & 7, dz = tid >> 6;
    const float* s = sa + dz * 100 + hy * 10 + wx;
    float m = -3.4e38f;
#pragma unroll
    for (int i = 0; i < 3; i++)
#pragma unroll
        for (int j = 0; j < 3; j++)
#pragma unroll
            for (int k = 0; k < 3; k++)
                m = fmaxf(m, s[i * 100 + j * 10 + k]);

    if (!(m > 0.1f)) {
        size_t sp = ((size_t)b << 22) + ((size_t)(d0 + dz) << 12) + ((h0 + hy) << 6) + (w0 + wx);
#pragma unroll
        for (int c = 0; c < 16; c++)
            out[sp + ((size_t)c << 18)] = 0.f;
    }
}

// ---------------------------------------------------------------------------
extern "C" void kernel_launch(void* const* d_in, const int* in_sizes, int n_in,
                              void* d_out, int out_size)
{
    const float* x   = (const float*)d_in[0];
    const float* rm  = (const float*)d_in[1];
    const float* W1  = (const float*)d_in[2];
    const float* b1  = (const float*)d_in[3];
    const float* W2  = (const float*)d_in[4];
    float* out = (float*)d_out;

    int B = in_sizes[0] >> 22;

    static int once = 0;
    if (!once) {
        cudaFuncSetAttribute(nca_pass1, cudaFuncAttributeMaxDynamicSharedMemorySize, SMEM_P1);
        once = 1;
    }

    // 5 launches/call; 4th overall = pass1 (ncu target slot)
    nca_prep<<<8, 256>>>(W1);
    nca_pad<<<1, 32>>>();
    nca_pad<<<1, 32>>>();
    nca_pass1<<<B << 11, 128, SMEM_P1>>>(x, rm, b1, W2, out);
    nca_pass2<<<B << 10, 256>>>(out);
}

// round 15
// speedup vs baseline: 1.4278x; 1.0803x over previous
#include <cuda_runtime.h>
#include <cuda_bf16.h>
#include <math.h>

// ---------------------------------------------------------------------------
// NCA_3D  (B=8, C=16, S=64, HID=32, fp32)
// R15: R14 + A-tile XOR swizzle + hoisted staging offsets.
//   - A-tile stores were 8-WAY conflicted (bank-pair = 4m+ch). Store pair-col
//     at ch ^ m (m = (row>>1)&15) -> (4m + (ch^m)) mod 16 is a bijection in m
//     -> uniform 2-way stores (optimal). Loads recompute the XOR (<=2-way).
//   - staging offsets channel-invariant, hoisted to 3 regs (alu was 52%).
// ---------------------------------------------------------------------------

typedef unsigned int u32;

__device__ u32  g_w1t[32 * 32];        // u32 pairs, [n][k2 ^ ((n&7)<<2)]
__device__ float g_alpha[8u << 18];

__device__ __forceinline__ u32 cvt_bf16x2(float hi, float lo) {
    u32 r; asm("cvt.rn.bf16x2.f32 %0, %1, %2;" : "=r"(r) : "f"(hi), "f"(lo)); return r;
}
__device__ __forceinline__ void mma16816(float* d, const u32* a, const u32* b) {
    asm("mma.sync.aligned.m16n8k16.row.col.f32.bf16.bf16.f32 "
        "{%0,%1,%2,%3}, {%4,%5,%6,%7}, {%8,%9}, {%0,%1,%2,%3};"
        : "+f"(d[0]), "+f"(d[1]), "+f"(d[2]), "+f"(d[3])
        : "r"(a[0]), "r"(a[1]), "r"(a[2]), "r"(a[3]), "r"(b[0]), "r"(b[1]));
}

#define S_SLAB 360            // 6d x 6h x 10w per channel
#define A_PITCH_U32 36        // 144 B row pitch
#define OFF_SLAB 0
#define OFF_A    23040
#define OFF_W1   41472        // 4096 B
#define SMEM_P1  45568        // 5 CTAs/SM incl. runtime reserve

// ---------------------------------------------------------------------------
__global__ void nca_prep(const float* __restrict__ W1)
{
    int t = blockIdx.x * 256 + threadIdx.x;
    __nv_bfloat16* w1 = (__nv_bfloat16*)g_w1t;
    if (t < 32 * 64) {
        int n = t >> 6, k = t & 63;
        float w = W1[n * 64 + (k & 3) * 16 + (k >> 2)];
        int k2 = k >> 1;
        int sw = k2 ^ ((n & 7) << 2);
        w1[(n * 32 + sw) * 2 + (k & 1)] = __float2bfloat16(w);
    }
}

__global__ void nca_pad() {}

// spatial offset for slab index r (6d x 6h x 10w halo), wrapped
__device__ __forceinline__ u32 slab_off(int r, int d0, int h0, int w0) {
    int sd = r / 60; int rem = r - sd * 60;
    int sh = rem / 10; int sw = rem - sh * 10;
    int gd = (d0 + sd - 1) & 63;
    int gh = (h0 + sh - 1) & 63;
    int gw = (w0 + sw - 1) & 63;
    return ((u32)gd << 12) + ((u32)gh << 6) + (u32)gw;
}

// ---------------------------------------------------------------------------
__global__ __launch_bounds__(128, 5)
void nca_pass1(const float* __restrict__ x, const float* __restrict__ rmask,
               const float* __restrict__ b1, const float* __restrict__ W2,
               float* __restrict__ out)
{
    extern __shared__ char smraw[];
    float* slab = (float*)(smraw + OFF_SLAB);
    u32*   Au   = (u32*)(smraw + OFF_A);
    u32*   w1u  = (u32*)(smraw + OFF_W1);

    int tid  = threadIdx.x;
    int warp = tid >> 5;
    int lane = tid & 31;
    int g = lane >> 2, c = lane & 3;

    int blk = blockIdx.x;
    int w0 = (blk & 7) << 3;
    int h0 = ((blk >> 3) & 15) << 2;
    int d0 = ((blk >> 7) & 15) << 2;
    int b  = blk >> 11;
    const size_t baseB = (size_t)b << 22;

    // ---- stage x slab (hoisted channel-invariant offsets) ----
    {
        u32 o0 = slab_off(tid, d0, h0, w0);
        u32 o1 = slab_off(tid + 128, d0, h0, w0);
        u32 o2 = (tid < S_SLAB - 256) ? slab_off(tid + 256, d0, h0, w0) : o0;
        const float* xb = x + baseB;
#pragma unroll 4
        for (int ch = 0; ch < 16; ch++) {
            const float* xc = xb + ((size_t)ch << 18);
            float* sc = slab + ch * S_SLAB;
            sc[tid]       = xc[o0];
            sc[tid + 128] = xc[o1];
            if (tid < S_SLAB - 256) sc[tid + 256] = xc[o2];
        }
    }
    // ---- stage W1 (uint4 copies of pre-swizzled image) ----
    {
        uint4* d1 = (uint4*)w1u; const uint4* s1 = (const uint4*)g_w1t;
        for (int i = tid; i < 256; i += 128) d1[i] = s1[i];
    }
    __syncthreads();

    // ---- Sobel: 2 voxels x 8 channels per thread; A-tile XOR-swizzled ----
    {
        int pairIdx = tid & 63;
        int chBase  = (tid >> 6) << 3;
        int vd = pairIdx >> 4, vh = (pairIdx >> 2) & 3, vw0 = (pairIdx & 3) << 1;
        int r = vd * 32 + vh * 8 + vw0;
        int m = (r >> 1) & 15;                 // swizzle key (shared by r, r+1)
        u32* Arow0 = Au + r * A_PITCH_U32;
        u32* Arow1 = Arow0 + A_PITCH_U32;
        const float* sbase = slab + chBase * S_SLAB + vd * 60 + vh * 10 + vw0;

#pragma unroll 2
        for (int cc = 0; cc < 8; cc++) {
            const float2* s2 = (const float2*)(sbase + cc * S_SLAB);

            float v[36];
#pragma unroll
            for (int i = 0; i < 3; i++)
#pragma unroll
                for (int j = 0; j < 3; j++) {
                    int half = (i * 60 + j * 10) >> 1;
                    float2 p0 = s2[half];
                    float2 p1 = s2[half + 1];
                    int o4 = (i * 3 + j) * 4;
                    v[o4 + 0] = p0.x; v[o4 + 1] = p0.y;
                    v[o4 + 2] = p1.x; v[o4 + 3] = p1.y;
                }

            float a[12];
#pragma unroll
            for (int j = 0; j < 3; j++)
#pragma unroll
                for (int k = 0; k < 4; k++)
                    a[j * 4 + k] = fmaf(2.f, v[(3 + j) * 4 + k], v[j * 4 + k] + v[(6 + j) * 4 + k]);

            float gx0 = fmaf(2.f, a[4 + 2] - a[4 + 0], (a[2] - a[0]) + (a[8 + 2] - a[8 + 0]));
            float gx1 = fmaf(2.f, a[4 + 3] - a[4 + 1], (a[3] - a[1]) + (a[8 + 3] - a[8 + 1]));

            float e0 = a[8] - a[0], e1 = a[9] - a[1], e2 = a[10] - a[2], e3 = a[11] - a[3];
            float gy0 = fmaf(2.f, e1, e0 + e2);
            float gy1 = fmaf(2.f, e2, e1 + e3);

            float rr[4];
#pragma unroll
            for (int k = 0; k < 4; k++) {
                float q0 = v[24 + k] - v[k];
                float q1 = v[28 + k] - v[4 + k];
                float q2 = v[32 + k] - v[8 + k];
                rr[k] = fmaf(2.f, q1, q0 + q2);
            }
            float gz0 = fmaf(2.f, rr[1], rr[0] + rr[2]);
            float gz1 = fmaf(2.f, rr[2], rr[1] + rr[3]);

            float xc0 = v[16 + 1], xc1 = v[16 + 2];

            int ko = ((chBase + cc) ^ m) * 2;   // swizzled pair column
            uint2 p0, p1;
            p0.x = cvt_bf16x2(gy0, gx0); p0.y = cvt_bf16x2(xc0, gz0);
            p1.x = cvt_bf16x2(gy1, gx1); p1.y = cvt_bf16x2(xc1, gz1);
            *(uint2*)(Arow0 + ko) = p0;
            *(uint2*)(Arow1 + ko) = p1;
        }
    }
    __syncthreads();

    // ---- GEMM1: M32 N32 K64 (both operands conflict-managed) ----
    float C1[2][4][4];
#pragma unroll
    for (int mt = 0; mt < 2; mt++)
#pragma unroll
        for (int nt = 0; nt < 4; nt++)
#pragma unroll
            for (int q = 0; q < 4; q++) C1[mt][nt][q] = 0.f;

    const int sw4g = g << 2;                   // W1 swizzle term
    const int par  = c & 1;                    // A-tile u32 parity
    const int ch2  = c >> 1;
#pragma unroll
    for (int kt = 0; kt < 4; kt++) {
        u32 Bk[4][2];
#pragma unroll
        for (int nt = 0; nt < 4; nt++) {
            int rowb = (g + 8 * nt) * 32;
            Bk[nt][0] = w1u[rowb + ((8 * kt + c) ^ sw4g)];
            Bk[nt][1] = w1u[rowb + ((8 * kt + c + 4) ^ sw4g)];
        }
        int pr = 4 * kt + ch2;                 // logical pair column
#pragma unroll
        for (int mt = 0; mt < 2; mt++) {
            int r0 = warp * 32 + mt * 16 + g;
            int mA = (mt * 8 + (g >> 1)) & 15;       // m for row r0 (and r0^1)
            int mB = mA + 4;                          // m for row r0+8
            int b0 = r0 * A_PITCH_U32;
            int b1r = b0 + 8 * A_PITCH_U32;
            u32 a[4];
            a[0] = Au[b0  + ((pr       ^ mA) * 2 + par)];
            a[1] = Au[b1r + ((pr       ^ mB) * 2 + par)];
            a[2] = Au[b0  + (((pr + 2) ^ mA) * 2 + par)];
            a[3] = Au[b1r + (((pr + 2) ^ mB) * 2 + par)];
#pragma unroll
            for (int nt = 0; nt < 4; nt++)
                mma16816(C1[mt][nt], a, Bk[nt]);
        }
    }

    // ---- bias + relu (bias from global, L1-hit) ----
#pragma unroll
    for (int nt = 0; nt < 4; nt++) {
        float2 bp = *(const float2*)(b1 + 2 * c + 8 * nt);
#pragma unroll
        for (int mt = 0; mt < 2; mt++) {
            C1[mt][nt][0] = fmaxf(C1[mt][nt][0] + bp.x, 0.f);
            C1[mt][nt][1] = fmaxf(C1[mt][nt][1] + bp.y, 0.f);
            C1[mt][nt][2] = fmaxf(C1[mt][nt][2] + bp.x, 0.f);
            C1[mt][nt][3] = fmaxf(C1[mt][nt][3] + bp.y, 0.f);
        }
    }

    // ---- repack C1 -> A2 fragments (registers only) ----
    u32 A2f[2][2][4];
#pragma unroll
    for (int mt = 0; mt < 2; mt++)
#pragma unroll
        for (int kt = 0; kt < 2; kt++) {
            A2f[mt][kt][0] = cvt_bf16x2(C1[mt][2 * kt][1],     C1[mt][2 * kt][0]);
            A2f[mt][kt][1] = cvt_bf16x2(C1[mt][2 * kt][3],     C1[mt][2 * kt][2]);
            A2f[mt][kt][2] = cvt_bf16x2(C1[mt][2 * kt + 1][1], C1[mt][2 * kt + 1][0]);
            A2f[mt][kt][3] = cvt_bf16x2(C1[mt][2 * kt + 1][3], C1[mt][2 * kt + 1][2]);
        }

    // ---- B2 fragments from global (contiguous float2, L1-hit; built late) ----
    u32 B2f[2][2][2];
#pragma unroll
    for (int nt = 0; nt < 2; nt++)
#pragma unroll
        for (int kt = 0; kt < 2; kt++) {
            const float* W2r = W2 + (g + 8 * nt) * 32;
            float2 plo = *(const float2*)(W2r + 2 * (8 * kt + c));
            float2 phi = *(const float2*)(W2r + 2 * (8 * kt + c + 4));
            B2f[nt][kt][0] = cvt_bf16x2(plo.y, plo.x);
            B2f[nt][kt][1] = cvt_bf16x2(phi.y, phi.x);
        }

    // ---- GEMM2: M32 N16 K32 ----
    float D2[2][2][4];
#pragma unroll
    for (int mt = 0; mt < 2; mt++)
#pragma unroll
        for (int nt = 0; nt < 2; nt++)
#pragma unroll
            for (int q = 0; q < 4; q++) D2[mt][nt][q] = 0.f;
#pragma unroll
    for (int kt = 0; kt < 2; kt++)
#pragma unroll
        for (int mt = 0; mt < 2; mt++)
#pragma unroll
            for (int nt = 0; nt < 2; nt++)
                mma16816(D2[mt][nt], A2f[mt][kt], B2f[nt][kt]);

    // ---- epilogue ----
    {
        int vw = g, vd = warp;
        int d = d0 + vd, ww = w0 + vw;
#pragma unroll
        for (int mt = 0; mt < 2; mt++)
#pragma unroll
            for (int h2 = 0; h2 < 2; h2++) {
                int vh = mt * 2 + h2;
                int hh = h0 + vh;
                size_t sp = ((size_t)d << 12) + (hh << 6) + ww;
                int sctr = (vd + 1) * 60 + (vh + 1) * 10 + (vw + 1);
#pragma unroll
                for (int nt = 0; nt < 2; nt++)
#pragma unroll
                    for (int lh = 0; lh < 2; lh++) {
                        int ch = 2 * c + lh + 8 * nt;
                        float dy = D2[mt][nt][h2 * 2 + lh];
                        float xv = slab[ch * S_SLAB + sctr];
                        size_t gi = baseB + ((size_t)ch << 18) + sp;
                        float u = floorf(rmask[gi] + 0.25f);
                        float y = fmaf(dy, u, xv);
                        out[gi] = y;
                        if (ch == 3) g_alpha[((size_t)b << 18) + sp] = y;
                    }
            }
    }
}

// ---------------------------------------------------------------------------
__global__ __launch_bounds__(256)
void nca_pass2(float* __restrict__ out)
{
    __shared__ float sa[600];

    int blk = blockIdx.x;
    int w0 = (blk & 7) << 3;
    int h0 = ((blk >> 3) & 7) << 3;
    int d0 = ((blk >> 6) & 15) << 2;
    int b  = blk >> 10;
    int tid = threadIdx.x;

    const float* ap = g_alpha + ((size_t)b << 18);
    for (int i = tid; i < 600; i += 256) {
        int dd = i / 100; int r = i - dd * 100;
        int hh = r / 10;  int ww = r - hh * 10;
        int gd = d0 + dd - 1, gh = h0 + hh - 1, gw = w0 + ww - 1;
        float val = -3.4e38f;
        if ((unsigned)gd < 64u && (unsigned)gh < 64u && (unsigned)gw < 64u)
            val = ap[((size_t)gd << 12) + (gh << 6) + gw];
        sa[i] = val;
    }
    __syncthreads();

    int wx = tid & 7, hy = (tid >> 3) & 7, dz = tid >> 6;
    const float* s = sa + dz * 100 + hy * 10 + wx;
    float m = -3.4e38f;
#pragma unroll
    for (int i = 0; i < 3; i++)
#pragma unroll
        for (int j = 0; j < 3; j++)
#pragma unroll
            for (int k = 0; k < 3; k++)
                m = fmaxf(m, s[i * 100 + j * 10 + k]);

    if (!(m > 0.1f)) {
        size_t sp = ((size_t)b << 22) + ((size_t)(d0 + dz) << 12) + ((h0 + hy) << 6) + (w0 + wx);
#pragma unroll
        for (int c = 0; c < 16; c++)
            out[sp + ((size_t)c << 18)] = 0.f;
    }
}

// ---------------------------------------------------------------------------
extern "C" void kernel_launch(void* const* d_in, const int* in_sizes, int n_in,
                              void* d_out, int out_size)
{
    const float* x   = (const float*)d_in[0];
    const float* rm  = (const float*)d_in[1];
    const float* W1  = (const float*)d_in[2];
    const float* b1  = (const float*)d_in[3];
    const float* W2  = (const float*)d_in[4];
    float* out = (float*)d_out;

    int B = in_sizes[0] >> 22;

    static int once = 0;
    if (!once) {
        cudaFuncSetAttribute(nca_pass1, cudaFuncAttributeMaxDynamicSharedMemorySize, SMEM_P1);
        once = 1;
    }

    // 5 launches/call; 4th overall = pass1 (ncu target slot)
    nca_prep<<<8, 256>>>(W1);
    nca_pad<<<1, 32>>>();
    nca_pad<<<1, 32>>>();
    nca_pass1<<<B << 11, 128, SMEM_P1>>>(x, rm, b1, W2, out);
    nca_pass2<<<B << 10, 256>>>(out);
}